// round 14
// baseline (speedup 1.0000x reference)
#include <cuda_runtime.h>
#include <cuda_bf16.h>

#define N_SEG 128
#define E 128
#define H 4
#define GRID  1332          // 3 perfect waves at 3 blocks/SM on 148 SMs
#define CHUNK 188           // ceil(250000/1332) rounded to multiple of 4
#define LOG2E 1.4426950408889634f

typedef unsigned long long ull;

__device__ float g_hsum[N_SEG * H * E];    // unnormalized weighted sums
__device__ float g_ssum[N_SEG * H];        // unnormalized softmax denominators

__device__ __forceinline__ float ex2f(float x) {
    float y;
    asm("ex2.approx.f32 %0, %1;" : "=f"(y) : "f"(x));
    return y;
}
__device__ __forceinline__ ull pack2(float a, float b) {
    ull r; asm("mov.b64 %0, {%1, %2};" : "=l"(r) : "f"(a), "f"(b)); return r;
}
__device__ __forceinline__ void unpack2(ull v, float& a, float& b) {
    asm("mov.b64 {%0, %1}, %2;" : "=f"(a), "=f"(b) : "l"(v));
}
__device__ __forceinline__ ull fma2(ull a, ull b, ull c) {
    ull d; asm("fma.rn.f32x2 %0, %1, %2, %3;" : "=l"(d) : "l"(a), "l"(b), "l"(c)); return d;
}
__device__ __forceinline__ ull mul2(ull a, ull b) {
    ull d; asm("mul.rn.f32x2 %0, %1, %2;" : "=l"(d) : "l"(a), "l"(b)); return d;
}

// ---------------------------------------------------------------------------
// Init: pure zeroing of accumulators (float4). 65 blocks — minimal.
// ---------------------------------------------------------------------------
__global__ void init_kernel() {
    int idx = blockIdx.x * 256 + threadIdx.x;     // float4 index
    if (idx < 16384) {
        ((float4*)g_hsum)[idx] = make_float4(0.f, 0.f, 0.f, 0.f);
    } else if (idx < 16512) {
        ((float4*)g_ssum)[idx - 16384] = make_float4(0.f, 0.f, 0.f, 0.f);
    }
}

// ---------------------------------------------------------------------------
// Main: uniform ROW-RANGE decomposition (no segment offsets needed).
// Block owns rows [bid*CHUNK, bid*CHUNK+CHUNK); warp processes 4-row batches.
// Each lane reads its batch id; segment crossings (rare: chunk=188 << min
// segment ~1800) flush the warp accumulator to a per-warp smem slice.
// Hot loop body identical to R13 (proven): f32x2 packed dots, 4-stage+1
// multi-value butterfly (lanes 2k,2k+1 -> complete dot of value k =
// (row k>>2, head k&3)), one ex2 per lane, packed accumulate.
// Block epilogue: group smem slices by distinct segment (<=2-3), tree
// reduce, one global atomicAdd pass per distinct segment.
// ---------------------------------------------------------------------------
__global__ void __launch_bounds__(256, 3)
main_kernel(const float* __restrict__ x, const float* __restrict__ weights,
            const int* __restrict__ batch, int N) {
    const int rstart = blockIdx.x * CHUNK;
    if (rstart >= N) return;                       // uniform: whole block exits
    const int rend = min(rstart + CHUNK, N);

    const int warp = threadIdx.x >> 5;
    const int lane = threadIdx.x & 31;
    const int myrow = lane >> 3;                   // row of this lane's value k = lane>>1

    // 16 slices: [warp][slot], each 512 floats + seg tag + 4 head sums
    __shared__ float wsl[16][H * E];               // 32 KB
    __shared__ float wsum_s[16][H];
    __shared__ int   wseg_s[16];
    __shared__ int   dsegs[16];
    __shared__ int   nd_s;
    if (threadIdx.x < 16) wseg_s[threadIdx.x] = -1;
    __syncthreads();

    // inline weight load + log2e scale, packed element pairs (L2-hot)
    const float* wl = weights + (lane << 2);
    ull wp[H][2];
    #pragma unroll
    for (int h = 0; h < H; h++) {
        wp[h][0] = pack2(wl[h * E + 0] * LOG2E, wl[h * E + 1] * LOG2E);
        wp[h][1] = pack2(wl[h * E + 2] * LOG2E, wl[h * E + 3] * LOG2E);
    }

    ull acc[H][2];
    #pragma unroll
    for (int h = 0; h < H; h++) { acc[h][0] = 0ull; acc[h][1] = 0ull; }
    float s = 0.f;
    int cur_seg = -1;
    int slot = 0;

    for (int base = rstart + warp * 4; base < rend; base += 32) {
        // ---- this lane's row's segment id (4 distinct addrs, 1 sector) ----
        const int r_l = base + myrow;
        const int lane_seg = (r_l < rend) ? batch[r_l] : cur_seg;

        // ---- load 4 rows ----
        ull xlo[4], xhi[4];
        #pragma unroll
        for (int i = 0; i < 4; i++) {
            const int rr = base + i;
            float4 v = (rr < rend)
                ? *(const float4*)(x + (size_t)rr * E + (lane << 2))
                : make_float4(0.f, 0.f, 0.f, 0.f);
            xlo[i] = pack2(v.x, v.y);
            xhi[i] = pack2(v.z, v.w);
        }

        // ---- 16 dot partials via packed FFMA2 ----
        float vals[16];
        #pragma unroll
        for (int i = 0; i < 4; i++) {
            #pragma unroll
            for (int h = 0; h < H; h++) {
                ull d = mul2(xlo[i], wp[h][0]);
                d = fma2(xhi[i], wp[h][1], d);
                float dl, dh;
                unpack2(d, dl, dh);
                vals[i * 4 + h] = dl + dh;
            }
        }

        // ---- multi-value butterfly over lane bits 4..1 + final xor-1 ----
        #pragma unroll
        for (int d = 8; d >= 1; d >>= 1) {
            #pragma unroll
            for (int i = 0; i < d; i++) {
                const bool up = (lane & (d << 1)) != 0;
                float give = up ? vals[i] : vals[i + d];
                float keep = up ? vals[i + d] : vals[i];
                vals[i] = keep + __shfl_xor_sync(0xFFFFFFFFu, give, d << 1);
            }
        }
        vals[0] += __shfl_xor_sync(0xFFFFFFFFu, vals[0], 1);

        // ---- one ex2 per lane; zero invalid rows ----
        float e = ex2f(vals[0]);
        if (r_l >= rend) e = 0.f;

        // ---- broadcast e per (row,head) ----
        float eb[4][4];
        #pragma unroll
        for (int i = 0; i < 4; i++)
            #pragma unroll
            for (int h = 0; h < H; h++)
                eb[i][h] = __shfl_sync(0xFFFFFFFFu, e, (i * 4 + h) << 1);

        const bool fast = __all_sync(0xFFFFFFFFu, lane_seg == cur_seg);
        if (fast) {
            s += e;
            #pragma unroll
            for (int i = 0; i < 4; i++) {
                const ull eb0 = pack2(eb[i][0], eb[i][0]);
                const ull eb1 = pack2(eb[i][1], eb[i][1]);
                const ull eb2 = pack2(eb[i][2], eb[i][2]);
                const ull eb3 = pack2(eb[i][3], eb[i][3]);
                acc[0][0] = fma2(eb0, xlo[i], acc[0][0]); acc[0][1] = fma2(eb0, xhi[i], acc[0][1]);
                acc[1][0] = fma2(eb1, xlo[i], acc[1][0]); acc[1][1] = fma2(eb1, xhi[i], acc[1][1]);
                acc[2][0] = fma2(eb2, xlo[i], acc[2][0]); acc[2][1] = fma2(eb2, xhi[i], acc[2][1]);
                acc[3][0] = fma2(eb3, xlo[i], acc[3][0]); acc[3][1] = fma2(eb3, xhi[i], acc[3][1]);
            }
        } else {
            // slow path: per-row segment tracking with flush on change
            #pragma unroll
            for (int i = 0; i < 4; i++) {
                if (base + i < rend) {                       // warp-uniform
                    const int si = __shfl_sync(0xFFFFFFFFu, lane_seg, i << 3);
                    if (si != cur_seg) {
                        // ---- flush accumulator to smem slice ----
                        if (cur_seg >= 0) {
                            float s2 = s + __shfl_xor_sync(0xFFFFFFFFu, s, 8);
                            s2 += __shfl_xor_sync(0xFFFFFFFFu, s2, 16);
                            const int idx = warp * 2 + slot;
                            float4* dsl = (float4*)wsl[idx];
                            #pragma unroll
                            for (int h = 0; h < H; h++) {
                                float4 v;
                                unpack2(acc[h][0], v.x, v.y);
                                unpack2(acc[h][1], v.z, v.w);
                                dsl[h * 32 + lane] = v;
                            }
                            if (lane < 8 && (lane & 1) == 0)
                                wsum_s[idx][lane >> 1] = s2;
                            if (lane == 0) wseg_s[idx] = cur_seg;
                            slot = 1;
                            #pragma unroll
                            for (int h = 0; h < H; h++) { acc[h][0] = 0ull; acc[h][1] = 0ull; }
                            s = 0.f;
                        }
                        cur_seg = si;
                    }
                    const ull eb0 = pack2(eb[i][0], eb[i][0]);
                    const ull eb1 = pack2(eb[i][1], eb[i][1]);
                    const ull eb2 = pack2(eb[i][2], eb[i][2]);
                    const ull eb3 = pack2(eb[i][3], eb[i][3]);
                    acc[0][0] = fma2(eb0, xlo[i], acc[0][0]); acc[0][1] = fma2(eb0, xhi[i], acc[0][1]);
                    acc[1][0] = fma2(eb1, xlo[i], acc[1][0]); acc[1][1] = fma2(eb1, xhi[i], acc[1][1]);
                    acc[2][0] = fma2(eb2, xlo[i], acc[2][0]); acc[2][1] = fma2(eb2, xhi[i], acc[2][1]);
                    acc[3][0] = fma2(eb3, xlo[i], acc[3][0]); acc[3][1] = fma2(eb3, xhi[i], acc[3][1]);
                    if (i == myrow) s += e;
                }
            }
        }
    }

    // ---- final flush of remaining accumulator ----
    if (cur_seg >= 0) {
        float s2 = s + __shfl_xor_sync(0xFFFFFFFFu, s, 8);
        s2 += __shfl_xor_sync(0xFFFFFFFFu, s2, 16);
        const int idx = warp * 2 + slot;
        float4* dsl = (float4*)wsl[idx];
        #pragma unroll
        for (int h = 0; h < H; h++) {
            float4 v;
            unpack2(acc[h][0], v.x, v.y);
            unpack2(acc[h][1], v.z, v.w);
            dsl[h * 32 + lane] = v;
        }
        if (lane < 8 && (lane & 1) == 0) wsum_s[idx][lane >> 1] = s2;
        if (lane == 0) wseg_s[idx] = cur_seg;
    }
    __syncthreads();

    // ---- gather distinct segments (<= 16, typically 1-2) ----
    if (threadIdx.x == 0) {
        int nd = 0;
        #pragma unroll
        for (int k = 0; k < 16; k++) {
            const int sg = wseg_s[k];
            if (sg >= 0) {
                bool seen = false;
                for (int j = 0; j < nd; j++) seen |= (dsegs[j] == sg);
                if (!seen) dsegs[nd++] = sg;
            }
        }
        nd_s = nd;
    }
    __syncthreads();

    const int nd = nd_s;
    for (int dd = 0; dd < nd; dd++) {
        const int sg = dsegs[dd];
        if (threadIdx.x < 128) {
            const int i = threadIdx.x;                 // float4 index
            float4 a4 = make_float4(0.f, 0.f, 0.f, 0.f);
            #pragma unroll
            for (int k = 0; k < 16; k++) {
                if (wseg_s[k] == sg) {
                    float4 t = ((const float4*)wsl[k])[i];
                    a4.x += t.x; a4.y += t.y; a4.z += t.z; a4.w += t.w;
                }
            }
            float* gh = g_hsum + sg * (H * E) + i * 4;
            atomicAdd(gh + 0, a4.x);
            atomicAdd(gh + 1, a4.y);
            atomicAdd(gh + 2, a4.z);
            atomicAdd(gh + 3, a4.w);
        } else if (threadIdx.x < 128 + H) {
            const int h = threadIdx.x - 128;
            float sv = 0.f;
            #pragma unroll
            for (int k = 0; k < 16; k++)
                if (wseg_s[k] == sg) sv += wsum_s[k][h];
            atomicAdd(&g_ssum[sg * H + h], sv);
        }
    }
}

// ---------------------------------------------------------------------------
// Finalize: out[b,e] = (1/H) * sum_h hsum[b,h,e] / ssum[b,h]
// ---------------------------------------------------------------------------
__global__ void final_kernel(float* __restrict__ out) {
    const int b = blockIdx.x;
    const int e = threadIdx.x;
    const float* hs = g_hsum + b * (H * E);
    const float* ss = g_ssum + b * H;
    float acc = 0.f;
    #pragma unroll
    for (int h = 0; h < H; h++) {
        const float s = ss[h];
        if (s > 0.f) acc += hs[h * E + e] / s;
    }
    out[b * E + e] = acc * (1.0f / H);
}

extern "C" void kernel_launch(void* const* d_in, const int* in_sizes, int n_in,
                              void* d_out, int out_size) {
    const float* x       = (const float*)d_in[0];
    const float* weights = (const float*)d_in[1];
    const int*   batch   = (const int*)d_in[2];
    float* out = (float*)d_out;
    const int N = in_sizes[0] / E;

    init_kernel<<<65, 256>>>();
    main_kernel<<<GRID, 256>>>(x, weights, batch, N);
    final_kernel<<<N_SEG, E>>>(out);
}